// round 7
// baseline (speedup 1.0000x reference)
#include <cuda_runtime.h>
#include <math.h>

#define LIST_CAP    4096
#define BLOOM_WORDS 256            // 8192 bits
#define BLOOM_MASK  8191u

__device__ int   g_keys[LIST_CAP]; // key = bq*N + dst
__device__ float g_wv[LIST_CAP];   // contribution value
__device__ int   g_cnt;            // reset by k_fix each call

__device__ __forceinline__ float final_elem(float a1, float a2)
{
    float t1 = 1.0f / (1.0f + __expf(-a1));
    float t2 = 1.0f / (1.0f + __expf(-a2));
    float tp = t1 * t2;
    const float EPS = 1e-10f;
    return __logf((tp + EPS) / (1.0f - tp + EPS));
}

// K1: blocks [0, SB): bloom-filtered edge scan, 8 edges/thread; on a match the
// warp computes dot(rel_emb[r]*w_out, rel_proj[t]) and appends (key, w) to the
// list. Blocks [SB, ...): const-fill out with final_elem(0,0).
__global__ void k_main(const int* __restrict__ e_index,
                       const int* __restrict__ r_index,
                       const int* __restrict__ edge_index,
                       const int* __restrict__ edge_type,
                       const float* __restrict__ rel_emb,
                       const float* __restrict__ rel_proj,
                       const float* __restrict__ w_out,
                       float* __restrict__ out,
                       int E, int nBQ, int D, int N, int outN, int SB, int FB)
{
    int tid = threadIdx.x;
    int bid = blockIdx.x;

    if (bid < SB) {
        __shared__ int      s_e[64];
        __shared__ int      s_r[64];
        __shared__ unsigned s_bloom[BLOOM_WORDS];
        for (int i = tid; i < BLOOM_WORDS; i += blockDim.x) s_bloom[i] = 0u;
        __syncthreads();
        if (tid < nBQ) {
            int ev = e_index[tid];
            s_e[tid] = ev;
            s_r[tid] = r_index[tid];
            unsigned h = (unsigned)ev & BLOOM_MASK;
            atomicOr(&s_bloom[h >> 5], 1u << (h & 31u));
        }
        __syncthreads();

        int base = (bid * blockDim.x + tid) * 8;
        int srcs[8];
        if (base + 7 < E) {
            int4 a = *(const int4*)(edge_index + base);
            int4 b = *(const int4*)(edge_index + base + 4);
            srcs[0]=a.x; srcs[1]=a.y; srcs[2]=a.z; srcs[3]=a.w;
            srcs[4]=b.x; srcs[5]=b.y; srcs[6]=b.z; srcs[7]=b.w;
        } else {
            #pragma unroll
            for (int j = 0; j < 8; j++)
                srcs[j] = (base + j < E) ? edge_index[base + j] : -1;
        }

        int lane = tid & 31;
        #pragma unroll
        for (int j = 0; j < 8; j++) {
            int src = srcs[j];
            bool maybe = false;
            if (src >= 0) {
                unsigned h = (unsigned)src & BLOOM_MASK;
                maybe = (s_bloom[h >> 5] >> (h & 31u)) & 1u;
            }
            if (!__ballot_sync(0xFFFFFFFFu, maybe)) continue;

            unsigned long long mm = 0ull;
            if (maybe) {
                for (int bq = 0; bq < nBQ; bq++)
                    mm |= ((unsigned long long)(src == s_e[bq])) << bq;
            }
            unsigned any = __ballot_sync(0xFFFFFFFFu, mm != 0ull);
            while (any) {
                int leader = __ffs(any) - 1;
                any &= any - 1;
                unsigned long long lm = __shfl_sync(0xFFFFFFFFu, mm, leader);
                int le  = __shfl_sync(0xFFFFFFFFu, base, leader) + j;
                int t   = edge_type[le];
                int dst = edge_index[E + le];
                const float* pt = rel_proj + (size_t)t * D;
                while (lm) {
                    int bq = __ffsll(lm) - 1;
                    lm &= lm - 1;
                    const float* pr = rel_emb + (size_t)s_r[bq] * D;
                    float s = 0.0f;
                    for (int d = lane; d < D; d += 32)
                        s += pr[d] * w_out[d] * pt[d];
                    #pragma unroll
                    for (int o = 16; o > 0; o >>= 1)
                        s += __shfl_xor_sync(0xFFFFFFFFu, s, o);
                    if (lane == 0) {
                        int idx = atomicAdd(&g_cnt, 1);
                        if (idx < LIST_CAP) {
                            g_keys[idx] = bq * N + dst;
                            g_wv[idx]   = s;
                        }
                    }
                }
            }
        }
    } else {
        // const fill: final_elem(0,0) = log(0.25/0.75)
        const float cv = -1.0986123f;
        float4 cv4 = make_float4(cv, cv, cv, cv);
        int f  = bid - SB;
        int n4 = outN >> 2;
        float4* out4 = (float4*)out;
        for (int k = f * blockDim.x + tid; k < n4; k += FB * blockDim.x)
            out4[k] = cv4;
        int tail = outN & 3;
        int i = f * blockDim.x + tid;
        if (i < tail) out[(n4 << 2) + i] = cv;
    }
}

// K2: one 1024-thread block. Concurrent speculative load of cnt + full list,
// shared-memory duplicate aggregation (entries with the same (b,dst) compute
// identical outputs — idempotent writes), then write touched outputs.
// No dense accumulator: nothing to re-zero except g_cnt.
__global__ void k_fix(float* __restrict__ out, int N)
{
    __shared__ int   s_cnt;
    __shared__ int   s_key[LIST_CAP];
    __shared__ float s_w[LIST_CAP];

    int tid = threadIdx.x;
    if (tid == 0) s_cnt = g_cnt;                 // issued concurrently with list loads
    for (int i = tid; i < LIST_CAP; i += blockDim.x) {
        s_key[i] = g_keys[i];
        s_w[i]   = g_wv[i];
    }
    __syncthreads();

    int cnt = s_cnt;
    if (cnt > LIST_CAP) cnt = LIST_CAP;

    for (int i = tid; i < cnt; i += blockDim.x) {
        int key = s_key[i];
        int bq  = key / N;
        int dst = key - bq * N;
        int b   = bq >> 1;
        int k1  = (2 * b) * N + dst;
        int k2  = k1 + N;
        float a1 = 0.0f, a2 = 0.0f;
        for (int j = 0; j < cnt; j++) {
            int   kj = s_key[j];
            float w  = s_w[j];
            a1 += (kj == k1) ? w : 0.0f;
            a2 += (kj == k2) ? w : 0.0f;
        }
        out[(size_t)b * N + dst] = final_elem(a1, a2);
    }
    __syncthreads();
    if (tid == 0) g_cnt = 0;
}

extern "C" void kernel_launch(void* const* d_in, const int* in_sizes, int n_in,
                              void* d_out, int out_size)
{
    // Input order: e_index, r_index, edge_index, edge_type, [num_nodes], rel_emb, rel_proj, w_out
    const int* e_index    = (const int*)d_in[0];
    const int* r_index    = (const int*)d_in[1];
    const int* edge_index = (const int*)d_in[2];
    const int* edge_type  = (const int*)d_in[3];
    int off = (n_in >= 8) ? 5 : 4;
    const float* rel_emb  = (const float*)d_in[off];
    const float* rel_proj = (const float*)d_in[off + 1];
    const float* w_out    = (const float*)d_in[off + 2];

    int nBQ = in_sizes[0];               // B*2
    int B   = nBQ / 2;
    int E   = in_sizes[3];               // edge_type is [E]
    int D   = in_sizes[off + 2];         // w_out is [D]
    int N   = out_size / B;              // output is [B, N]
    int outN = out_size;

    const int TPB = 256;
    int SB = (E + TPB * 8 - 1) / (TPB * 8);
    int n4 = outN >> 2;
    int FB = (n4 + TPB * 2 - 1) / (TPB * 2);
    if (FB < 1) FB = 1;
    int grid = SB + FB;

    k_main<<<grid, TPB>>>(e_index, r_index, edge_index, edge_type,
                          rel_emb, rel_proj, w_out, (float*)d_out,
                          E, nBQ, D, N, outN, SB, FB);
    k_fix<<<1, 1024>>>((float*)d_out, N);
}

// round 8
// speedup vs baseline: 1.0038x; 1.0038x over previous
#include <cuda_runtime.h>
#include <math.h>

#define ACC_CAP     (1 << 21)
#define LIST_CAP    1024
#define BLOOM_WORDS 256            // 8192 bits
#define BLOOM_MASK  8191u
#define EPT         16             // edges per thread in scan

__device__ float g_acc[ACC_CAP];   // zero-init; k_fix restores zeros each call
__device__ int2  g_list[LIST_CAP]; // (bq, dst)
__device__ int   g_cnt;            // reset by k_fix

__device__ __forceinline__ float final_elem(float a1, float a2)
{
    float t1 = 1.0f / (1.0f + __expf(-a1));
    float t2 = 1.0f / (1.0f + __expf(-a2));
    float tp = t1 * t2;
    const float EPS = 1e-10f;
    return __logf((tp + EPS) / (1.0f - tp + EPS));
}

// K1: blocks [0, SB): bloom-filtered edge scan, 16 edges/thread; on a match
// the warp computes dot(rel_emb[r]*w_out, rel_proj[t]), atomically accumulates
// into g_acc, records (bq, dst). Blocks [SB, ...): const-fill out.
// Grid sized to exactly one wave (148 blocks).
__global__ void k_main(const int* __restrict__ e_index,
                       const int* __restrict__ r_index,
                       const int* __restrict__ edge_index,
                       const int* __restrict__ edge_type,
                       const float* __restrict__ rel_emb,
                       const float* __restrict__ rel_proj,
                       const float* __restrict__ w_out,
                       float* __restrict__ out,
                       int E, int nBQ, int D, int N, int outN, int SB, int FB)
{
    int tid = threadIdx.x;
    int bid = blockIdx.x;

    if (bid < SB) {
        __shared__ int      s_e[64];
        __shared__ int      s_r[64];
        __shared__ unsigned s_bloom[BLOOM_WORDS];
        for (int i = tid; i < BLOOM_WORDS; i += blockDim.x) s_bloom[i] = 0u;
        __syncthreads();
        if (tid < nBQ) {
            int ev = e_index[tid];
            s_e[tid] = ev;
            s_r[tid] = r_index[tid];
            unsigned h = (unsigned)ev & BLOOM_MASK;
            atomicOr(&s_bloom[h >> 5], 1u << (h & 31u));
        }
        __syncthreads();

        int base = (bid * blockDim.x + tid) * EPT;
        int srcs[EPT];
        if (base + EPT - 1 < E) {
            #pragma unroll
            for (int v = 0; v < EPT / 4; v++) {
                int4 a = *(const int4*)(edge_index + base + v * 4);
                srcs[v*4+0]=a.x; srcs[v*4+1]=a.y; srcs[v*4+2]=a.z; srcs[v*4+3]=a.w;
            }
        } else {
            #pragma unroll
            for (int j = 0; j < EPT; j++)
                srcs[j] = (base + j < E) ? edge_index[base + j] : -1;
        }

        int lane = tid & 31;
        #pragma unroll
        for (int j = 0; j < EPT; j++) {
            int src = srcs[j];
            bool maybe = false;
            if (src >= 0) {
                unsigned h = (unsigned)src & BLOOM_MASK;
                maybe = (s_bloom[h >> 5] >> (h & 31u)) & 1u;
            }
            if (!__ballot_sync(0xFFFFFFFFu, maybe)) continue;

            unsigned long long mm = 0ull;
            if (maybe) {
                for (int bq = 0; bq < nBQ; bq++)
                    mm |= ((unsigned long long)(src == s_e[bq])) << bq;
            }
            unsigned any = __ballot_sync(0xFFFFFFFFu, mm != 0ull);
            while (any) {
                int leader = __ffs(any) - 1;
                any &= any - 1;
                unsigned long long lm = __shfl_sync(0xFFFFFFFFu, mm, leader);
                int le  = __shfl_sync(0xFFFFFFFFu, base, leader) + j;
                int t   = edge_type[le];
                int dst = edge_index[E + le];
                const float* pt = rel_proj + (size_t)t * D;
                while (lm) {
                    int bq = __ffsll(lm) - 1;
                    lm &= lm - 1;
                    const float* pr = rel_emb + (size_t)s_r[bq] * D;
                    float s = 0.0f;
                    for (int d = lane; d < D; d += 32)
                        s += pr[d] * w_out[d] * pt[d];
                    #pragma unroll
                    for (int o = 16; o > 0; o >>= 1)
                        s += __shfl_xor_sync(0xFFFFFFFFu, s, o);
                    if (lane == 0) {
                        atomicAdd(&g_acc[(size_t)bq * N + dst], s);
                        int idx = atomicAdd(&g_cnt, 1);
                        if (idx < LIST_CAP) g_list[idx] = make_int2(bq, dst);
                    }
                }
            }
        }
    } else {
        // const fill: final_elem(0,0) = log(0.25/0.75)
        const float cv = -1.0986123f;
        float4 cv4 = make_float4(cv, cv, cv, cv);
        int f  = bid - SB;
        int n4 = outN >> 2;
        float4* out4 = (float4*)out;
        for (int k = f * blockDim.x + tid; k < n4; k += FB * blockDim.x)
            out4[k] = cv4;
        int tail = outN & 3;
        int i = f * blockDim.x + tid;
        if (i < tail) out[(n4 << 2) + i] = cv;
    }
}

// K2: 1024 threads, one list entry per thread. g_cnt and g_list[tid] load
// concurrently (speculative single-entry load), so the dependent chain is just
// list -> acc -> out (2 memory round-trips). Duplicate (bq,dst) entries write
// identical outputs (acc already holds the full sum) — benign. Phase 2 zeros
// the touched acc entries (fire-and-forget stores) and resets the counter.
__global__ void k_fix(float* __restrict__ out, int N)
{
    int tid = threadIdx.x;
    int cnt  = g_cnt;            // independent loads, issued back-to-back
    int2 en  = g_list[tid];      // speculative (always in-bounds)
    if (cnt > LIST_CAP) cnt = LIST_CAP;

    int b = en.x >> 1, n = en.y;
    if (tid < cnt) {
        float a1 = g_acc[(size_t)(2 * b)     * N + n];
        float a2 = g_acc[(size_t)(2 * b + 1) * N + n];
        out[(size_t)b * N + n] = final_elem(a1, a2);
    }
    __syncthreads();
    if (tid < cnt) {
        g_acc[(size_t)(2 * b)     * N + n] = 0.0f;
        g_acc[(size_t)(2 * b + 1) * N + n] = 0.0f;
    }
    if (tid == 0) g_cnt = 0;
}

extern "C" void kernel_launch(void* const* d_in, const int* in_sizes, int n_in,
                              void* d_out, int out_size)
{
    // Input order: e_index, r_index, edge_index, edge_type, [num_nodes], rel_emb, rel_proj, w_out
    const int* e_index    = (const int*)d_in[0];
    const int* r_index    = (const int*)d_in[1];
    const int* edge_index = (const int*)d_in[2];
    const int* edge_type  = (const int*)d_in[3];
    int off = (n_in >= 8) ? 5 : 4;
    const float* rel_emb  = (const float*)d_in[off];
    const float* rel_proj = (const float*)d_in[off + 1];
    const float* w_out    = (const float*)d_in[off + 2];

    int nBQ = in_sizes[0];               // B*2
    int B   = nBQ / 2;
    int E   = in_sizes[3];               // edge_type is [E]
    int D   = in_sizes[off + 2];         // w_out is [D]
    int N   = out_size / B;              // output is [B, N]
    int outN = out_size;

    const int TPB = 256;
    int SB = (E + TPB * EPT - 1) / (TPB * EPT);   // 74 for E=300000
    int FB = 148 - SB;                            // fill the rest of one wave
    if (FB < 1) FB = 1;
    int grid = SB + FB;

    k_main<<<grid, TPB>>>(e_index, r_index, edge_index, edge_type,
                          rel_emb, rel_proj, w_out, (float*)d_out,
                          E, nBQ, D, N, outN, SB, FB);
    k_fix<<<1, 1024>>>((float*)d_out, N);
}

// round 9
// speedup vs baseline: 1.3208x; 1.3158x over previous
#include <cuda_runtime.h>
#include <math.h>

#define ACC_CAP     (1 << 21)
#define LIST_CAP    1024
#define BLOOM_WORDS 256            // 8192 bits
#define BLOOM_MASK  8191u
#define EPT         8              // edges per thread in scan (R6-proven)

__device__ float g_acc[ACC_CAP];   // zero-init; k_fix restores zeros each call
__device__ int2  g_list[LIST_CAP]; // (bq, dst)
__device__ int   g_cnt;            // reset by k_fix

__device__ __forceinline__ float final_elem(float a1, float a2)
{
    float t1 = 1.0f / (1.0f + __expf(-a1));
    float t2 = 1.0f / (1.0f + __expf(-a2));
    float tp = t1 * t2;
    const float EPS = 1e-10f;
    return __logf((tp + EPS) / (1.0f - tp + EPS));
}

// K1: blocks [0, SB): bloom-filtered edge scan, 8 edges/thread; on a match the
// warp computes dot(rel_emb[r]*w_out, rel_proj[t]), accumulates into g_acc,
// records (bq, dst). Blocks [SB, ...): const-fill out with final_elem(0,0).
__global__ void k_main(const int* __restrict__ e_index,
                       const int* __restrict__ r_index,
                       const int* __restrict__ edge_index,
                       const int* __restrict__ edge_type,
                       const float* __restrict__ rel_emb,
                       const float* __restrict__ rel_proj,
                       const float* __restrict__ w_out,
                       float* __restrict__ out,
                       int E, int nBQ, int D, int N, int outN, int SB, int FB)
{
    int tid = threadIdx.x;
    int bid = blockIdx.x;

    if (bid < SB) {
        __shared__ int      s_e[64];
        __shared__ int      s_r[64];
        __shared__ unsigned s_bloom[BLOOM_WORDS];
        for (int i = tid; i < BLOOM_WORDS; i += blockDim.x) s_bloom[i] = 0u;
        __syncthreads();
        if (tid < nBQ) {
            int ev = e_index[tid];
            s_e[tid] = ev;
            s_r[tid] = r_index[tid];
            unsigned h = (unsigned)ev & BLOOM_MASK;
            atomicOr(&s_bloom[h >> 5], 1u << (h & 31u));
        }
        __syncthreads();

        int base = (bid * blockDim.x + tid) * EPT;
        int srcs[EPT];
        if (base + EPT - 1 < E) {
            #pragma unroll
            for (int v = 0; v < EPT / 4; v++) {
                int4 a = *(const int4*)(edge_index + base + v * 4);
                srcs[v*4+0]=a.x; srcs[v*4+1]=a.y; srcs[v*4+2]=a.z; srcs[v*4+3]=a.w;
            }
        } else {
            #pragma unroll
            for (int j = 0; j < EPT; j++)
                srcs[j] = (base + j < E) ? edge_index[base + j] : -1;
        }

        int lane = tid & 31;
        #pragma unroll
        for (int j = 0; j < EPT; j++) {
            int src = srcs[j];
            bool maybe = false;
            if (src >= 0) {
                unsigned h = (unsigned)src & BLOOM_MASK;
                maybe = (s_bloom[h >> 5] >> (h & 31u)) & 1u;
            }
            if (!__ballot_sync(0xFFFFFFFFu, maybe)) continue;

            unsigned long long mm = 0ull;
            if (maybe) {
                for (int bq = 0; bq < nBQ; bq++)
                    mm |= ((unsigned long long)(src == s_e[bq])) << bq;
            }
            unsigned any = __ballot_sync(0xFFFFFFFFu, mm != 0ull);
            while (any) {
                int leader = __ffs(any) - 1;
                any &= any - 1;
                unsigned long long lm = __shfl_sync(0xFFFFFFFFu, mm, leader);
                int le  = __shfl_sync(0xFFFFFFFFu, base, leader) + j;
                int t   = edge_type[le];
                int dst = edge_index[E + le];
                const float* pt = rel_proj + (size_t)t * D;
                while (lm) {
                    int bq = __ffsll(lm) - 1;
                    lm &= lm - 1;
                    const float* pr = rel_emb + (size_t)s_r[bq] * D;
                    float s = 0.0f;
                    for (int d = lane; d < D; d += 32)
                        s += pr[d] * w_out[d] * pt[d];
                    #pragma unroll
                    for (int o = 16; o > 0; o >>= 1)
                        s += __shfl_xor_sync(0xFFFFFFFFu, s, o);
                    if (lane == 0) {
                        atomicAdd(&g_acc[(size_t)bq * N + dst], s);
                        int idx = atomicAdd(&g_cnt, 1);
                        if (idx < LIST_CAP) g_list[idx] = make_int2(bq, dst);
                    }
                }
            }
        }
    } else {
        // const fill: final_elem(0,0) = log(0.25/0.75)
        const float cv = -1.0986123f;
        float4 cv4 = make_float4(cv, cv, cv, cv);
        int f  = bid - SB;
        int n4 = outN >> 2;
        float4* out4 = (float4*)out;
        for (int k = f * blockDim.x + tid; k < n4; k += FB * blockDim.x)
            out4[k] = cv4;
        int tail = outN & 3;
        int i = f * blockDim.x + tid;
        if (i < tail) out[(n4 << 2) + i] = cv;
    }
}

// K2 (PDL secondary): launched with programmatic stream serialization so its
// launch/prologue overlaps k_main; cudaGridDependencySynchronize() blocks
// until k_main's writes are visible. Then: speculative one-entry-per-thread
// list load, acc read -> out write, sync, fire-and-forget acc re-zero.
__global__ void k_fix(float* __restrict__ out, int N)
{
    cudaGridDependencySynchronize();

    int tid = threadIdx.x;
    int cnt  = g_cnt;            // independent loads, issued back-to-back
    int2 en  = g_list[tid];      // speculative (always in-bounds; LIST_CAP=1024)
    if (cnt > LIST_CAP) cnt = LIST_CAP;

    int b = en.x >> 1, n = en.y;
    if (tid < cnt) {
        float a1 = g_acc[(size_t)(2 * b)     * N + n];
        float a2 = g_acc[(size_t)(2 * b + 1) * N + n];
        out[(size_t)b * N + n] = final_elem(a1, a2);
    }
    __syncthreads();
    if (tid < cnt) {
        g_acc[(size_t)(2 * b)     * N + n] = 0.0f;
        g_acc[(size_t)(2 * b + 1) * N + n] = 0.0f;
    }
    if (tid == 0) g_cnt = 0;
}

extern "C" void kernel_launch(void* const* d_in, const int* in_sizes, int n_in,
                              void* d_out, int out_size)
{
    // Input order: e_index, r_index, edge_index, edge_type, [num_nodes], rel_emb, rel_proj, w_out
    const int* e_index    = (const int*)d_in[0];
    const int* r_index    = (const int*)d_in[1];
    const int* edge_index = (const int*)d_in[2];
    const int* edge_type  = (const int*)d_in[3];
    int off = (n_in >= 8) ? 5 : 4;
    const float* rel_emb  = (const float*)d_in[off];
    const float* rel_proj = (const float*)d_in[off + 1];
    const float* w_out    = (const float*)d_in[off + 2];

    int nBQ = in_sizes[0];               // B*2
    int B   = nBQ / 2;
    int E   = in_sizes[3];               // edge_type is [E]
    int D   = in_sizes[off + 2];         // w_out is [D]
    int N   = out_size / B;              // output is [B, N]
    int outN = out_size;

    const int TPB = 256;
    int SB = (E + TPB * EPT - 1) / (TPB * EPT);   // 147 for E=300000
    int n4 = outN >> 2;
    int FB = (n4 + TPB * 2 - 1) / (TPB * 2);      // ~2 float4 iters/thread
    if (FB < 1) FB = 1;
    int grid = SB + FB;

    k_main<<<grid, TPB>>>(e_index, r_index, edge_index, edge_type,
                          rel_emb, rel_proj, w_out, (float*)d_out,
                          E, nBQ, D, N, outN, SB, FB);

    // k_fix via PDL: overlap its launch with k_main's tail.
    cudaLaunchConfig_t cfg = {};
    cfg.gridDim  = dim3(1, 1, 1);
    cfg.blockDim = dim3(1024, 1, 1);
    cfg.dynamicSmemBytes = 0;
    cfg.stream = 0;
    cudaLaunchAttribute attr[1];
    attr[0].id = cudaLaunchAttributeProgrammaticStreamSerialization;
    attr[0].val.programmaticStreamSerializationAllowed = 1;
    cfg.attrs = attr;
    cfg.numAttrs = 1;
    cudaLaunchKernelEx(&cfg, k_fix, (float*)d_out, N);
}